// round 1
// baseline (speedup 1.0000x reference)
#include <cuda_runtime.h>
#include <math.h>

#define EPS 1e-4f

#define B_SZ   64
#define C_SZ   512
#define HW_SZ  196
#define P_SZ   2000

#define MT 128
#define NT 112
#define KT 16

// Scratch for precomputed norms (no cudaMalloc allowed).
__device__ float g_x2[B_SZ * HW_SZ];
__device__ float g_p2[2048];

// x2[b,hw] = sum_c x[b,c,hw]^2
__global__ void x2_kernel(const float* __restrict__ x) {
    int i = blockIdx.x * 256 + threadIdx.x;
    if (i >= B_SZ * HW_SZ) return;
    int b = i / HW_SZ, hw = i - b * HW_SZ;
    const float* px = x + (size_t)b * C_SZ * HW_SZ + hw;
    float s = 0.f;
#pragma unroll 8
    for (int c = 0; c < C_SZ; c++) {
        float v = px[(size_t)c * HW_SZ];
        s = fmaf(v, v, s);
    }
    g_x2[i] = s;
}

// p2[m] = sum_c prototypes[m,c]^2   (one warp per row)
__global__ void p2_kernel(const float* __restrict__ p) {
    int row  = blockIdx.x * 8 + (threadIdx.x >> 5);
    int lane = threadIdx.x & 31;
    float s = 0.f;
    if (row < P_SZ) {
        const float* pr = p + (size_t)row * C_SZ;
#pragma unroll
        for (int t = lane; t < C_SZ; t += 32) {
            float v = pr[t];
            s = fmaf(v, v, s);
        }
    }
#pragma unroll
    for (int o = 16; o > 0; o >>= 1)
        s += __shfl_down_sync(0xffffffffu, s, o);
    if (row < P_SZ && lane == 0) g_p2[row] = s;
}

// Main fused kernel: batched GEMM (P[2000,512] @ X_b[512,196]) + distance/log epilogue.
// grid: (2 n-tiles, 16 m-tiles, 64 batches), 256 threads, each thread 8x7 outputs.
__global__ __launch_bounds__(256) void proto_kernel(
    const float* __restrict__ x,
    const float* __restrict__ p,
    float* __restrict__ out)
{
    __shared__ float Ps[KT][MT + 1];   // [k][m], padded
    __shared__ float Xs[KT][NT];       // [k][n]

    const int tid = threadIdx.x;
    const int tx  = tid & 15;          // n group
    const int ty  = tid >> 4;          // m group
    const int nb  = blockIdx.x * NT;   // 0 or 112
    const int mb  = blockIdx.y * MT;
    const int b   = blockIdx.z;

    const float* xb = x + (size_t)b * C_SZ * HW_SZ;

    float acc[8][7];
#pragma unroll
    for (int i = 0; i < 8; i++)
#pragma unroll
        for (int j = 0; j < 7; j++) acc[i][j] = 0.f;

    for (int kt = 0; kt < C_SZ; kt += KT) {
        // Load P tile: 128x16 floats (8 per thread). Consecutive tid -> consecutive k
        // within a row: 64B segments, coalesced.
#pragma unroll
        for (int l = 0; l < 8; l++) {
            int idx = tid + l * 256;
            int m = idx >> 4, k = idx & 15;
            int mg = mb + m;
            Ps[k][m] = (mg < P_SZ) ? p[(size_t)mg * C_SZ + kt + k] : 0.f;
        }
        // Load X tile: 16x112 floats (7 per thread), coalesced along hw.
#pragma unroll
        for (int l = 0; l < 7; l++) {
            int idx = tid + l * 256;
            int k = idx / NT, n = idx - k * NT;
            int hw = nb + n;
            Xs[k][n] = (hw < HW_SZ) ? xb[(size_t)(kt + k) * HW_SZ + hw] : 0.f;
        }
        __syncthreads();

#pragma unroll
        for (int k = 0; k < KT; k++) {
            float pv[8], xv[7];
#pragma unroll
            for (int i = 0; i < 8; i++) pv[i] = Ps[k][ty + i * 16];
#pragma unroll
            for (int j = 0; j < 7; j++) xv[j] = Xs[k][tx + j * 16];
#pragma unroll
            for (int i = 0; i < 8; i++)
#pragma unroll
                for (int j = 0; j < 7; j++)
                    acc[i][j] = fmaf(pv[i], xv[j], acc[i][j]);
        }
        __syncthreads();
    }

    // Fused epilogue: dist = max(x2 - 2*xp + p2, 0); act = log((dist+1)/(dist+EPS))
    float x2v[7];
    bool  nok[7];
#pragma unroll
    for (int j = 0; j < 7; j++) {
        int hw = nb + tx + j * 16;
        nok[j] = (hw < HW_SZ);
        x2v[j] = nok[j] ? g_x2[b * HW_SZ + hw] : 0.f;
    }

#pragma unroll
    for (int i = 0; i < 8; i++) {
        int m = mb + ty + i * 16;
        if (m < P_SZ) {
            float p2 = g_p2[m];
            float* orow = out + ((size_t)b * P_SZ + m) * HW_SZ;
#pragma unroll
            for (int j = 0; j < 7; j++) {
                if (nok[j]) {
                    int hw = nb + tx + j * 16;
                    float dist = fmaxf(x2v[j] - 2.f * acc[i][j] + p2, 0.f);
                    orow[hw] = logf((dist + 1.0f) / (dist + EPS));
                }
            }
        }
    }
}

extern "C" void kernel_launch(void* const* d_in, const int* in_sizes, int n_in,
                              void* d_out, int out_size) {
    const float* x = (const float*)d_in[0];   // (64, 512, 14, 14)
    const float* p = (const float*)d_in[1];   // (2000, 512, 1, 1) contiguous
    float* out = (float*)d_out;               // (64, 2000, 14, 14)

    x2_kernel<<<(B_SZ * HW_SZ + 255) / 256, 256>>>(x);
    p2_kernel<<<(P_SZ + 7) / 8, 256>>>(p);

    dim3 grid(2, (P_SZ + MT - 1) / MT, B_SZ);   // (2, 16, 64)
    proto_kernel<<<grid, 256>>>(x, p, out);
}

// round 3
// speedup vs baseline: 3.2191x; 3.2191x over previous
#include <cuda_runtime.h>
#include <cstdint>
#include <math.h>

#define EPS 1e-4f
#define B_SZ   64
#define C_SZ   512
#define HW_SZ  196
#define P_SZ   2000
#define MT     128
#define NT     112
#define KC     32
#define NSTAGE 16
#define APITCH 36
#define BPITCH 120
#define EPITCH 113

#define A_STG (MT*APITCH)              // 4608 floats
#define B_STG (KC*BPITCH)              // 3840 floats
#define SM_A0 0
#define SM_A1 A_STG
#define SM_B0 (2*A_STG)
#define SM_B1 (2*A_STG + B_STG)
#define SMEM_FLOATS (2*A_STG + 2*B_STG)   // 16896 floats = 67584 B
#define SMEM_BYTES  (SMEM_FLOATS*4)

static __device__ __forceinline__ uint32_t s2u(const void* p) {
    uint32_t a;
    asm("{ .reg .u64 t; cvta.to.shared.u64 t, %1; cvt.u32.u64 %0, t; }"
        : "=r"(a) : "l"(p));
    return a;
}

static __device__ __forceinline__ void cpa16(uint32_t dst, const void* src, int sz) {
    asm volatile("cp.async.cg.shared.global [%0], [%1], 16, %2;"
                 :: "r"(dst), "l"(src), "r"(sz));
}

static __device__ __forceinline__ void mma_tf32(
    float& c0, float& c1, float& c2, float& c3,
    float a0, float a1, float a2, float a3, float b0, float b1)
{
    asm volatile(
        "mma.sync.aligned.m16n8k8.row.col.f32.tf32.tf32.f32 "
        "{%0,%1,%2,%3}, {%4,%5,%6,%7}, {%8,%9}, {%0,%1,%2,%3};"
        : "+f"(c0), "+f"(c1), "+f"(c2), "+f"(c3)
        : "r"(__float_as_uint(a0)), "r"(__float_as_uint(a1)),
          "r"(__float_as_uint(a2)), "r"(__float_as_uint(a3)),
          "r"(__float_as_uint(b0)), "r"(__float_as_uint(b1)));
}

__global__ __launch_bounds__(256, 2) void proto_mma(
    const float* __restrict__ x,
    const float* __restrict__ p,
    float* __restrict__ out)
{
    extern __shared__ float smf[];
    const uint32_t sb = s2u(smf);
    const int tid  = threadIdx.x;
    const int wid  = tid >> 5;
    const int lane = tid & 31;
    const int qr   = lane >> 2;      // groupID
    const int qc   = lane & 3;       // threadID-in-group
    const int nb   = blockIdx.x * NT;
    const int mb   = blockIdx.y * MT;
    const int b    = blockIdx.z;
    const int mw   = (wid >> 1) * 32;   // warp M offset (0,32,64,96)
    const int nw   = (wid & 1) * 56;    // warp N offset (0,56)
    const float* xb = x + (size_t)b * C_SZ * HW_SZ;

    float acc[2][7][4];
#pragma unroll
    for (int i = 0; i < 2; i++)
#pragma unroll
        for (int j = 0; j < 7; j++)
#pragma unroll
            for (int r = 0; r < 4; r++) acc[i][j][r] = 0.f;
    float pa2[2][2] = {{0.f,0.f},{0.f,0.f}};
    float xb2[7]    = {0.f,0.f,0.f,0.f,0.f,0.f,0.f};

    // ---- async tile loader ----
    auto load_stage = [&](int s) {
        const int buf = s & 1;
        const int kt  = s * KC;
        const uint32_t sA = sb + (buf ? SM_A1 : SM_A0) * 4;
        const uint32_t sB = sb + (buf ? SM_B1 : SM_B0) * 4;
        // A: 128 rows x 8 float4  (1024 float4)
#pragma unroll
        for (int l = 0; l < 4; l++) {
            int idx = tid + l * 256;
            int row = idx >> 3, j = idx & 7;
            int sz  = (mb + row < P_SZ) ? 16 : 0;
            cpa16(sA + (row * APITCH + j * 4) * 4,
                  p + (size_t)(mb + row) * C_SZ + kt + j * 4, sz);
        }
        // B: 32 k-rows x 28 float4 (896 float4)
#pragma unroll
        for (int l = 0; l < 4; l++) {
            int idx = tid + l * 256;
            if (idx < 896) {
                int k = idx / 28, q = idx - k * 28;
                int n0 = nb + q * 4;
                int sz = (n0 <= HW_SZ - 4) ? 16 : 0;
                cpa16(sB + (k * BPITCH + q * 4) * 4,
                      xb + (size_t)(kt + k) * HW_SZ + n0, sz);
            }
        }
        asm volatile("cp.async.commit_group;" ::: "memory");
    };

    load_stage(0);

    for (int s = 0; s < NSTAGE; s++) {
        if (s + 1 < NSTAGE) load_stage(s + 1);
        else asm volatile("cp.async.commit_group;" ::: "memory");
        asm volatile("cp.async.wait_group 1;" ::: "memory");
        __syncthreads();

        const int buf = s & 1;
        const float* Ab = smf + (buf ? SM_A1 : SM_A0);
        const float* Bb = smf + (buf ? SM_B1 : SM_B0);
        const float* ap = Ab + (mw + qr) * APITCH + qc;
        const float* bp = Bb + qc * BPITCH + nw + qr;

#pragma unroll
        for (int ks = 0; ks < 4; ks++) {
            const int k8 = ks * 8;
            float af[2][4];
#pragma unroll
            for (int i = 0; i < 2; i++) {
                af[i][0] = ap[(16*i    ) * APITCH + k8    ];
                af[i][1] = ap[(16*i + 8) * APITCH + k8    ];
                af[i][2] = ap[(16*i    ) * APITCH + k8 + 4];
                af[i][3] = ap[(16*i + 8) * APITCH + k8 + 4];
                pa2[i][0] = fmaf(af[i][0], af[i][0], fmaf(af[i][2], af[i][2], pa2[i][0]));
                pa2[i][1] = fmaf(af[i][1], af[i][1], fmaf(af[i][3], af[i][3], pa2[i][1]));
            }
#pragma unroll
            for (int j = 0; j < 7; j++) {
                float b0 = bp[ k8      * BPITCH + 8*j];
                float b1 = bp[(k8 + 4) * BPITCH + 8*j];
                xb2[j] = fmaf(b0, b0, fmaf(b1, b1, xb2[j]));
                mma_tf32(acc[0][j][0], acc[0][j][1], acc[0][j][2], acc[0][j][3],
                         af[0][0], af[0][1], af[0][2], af[0][3], b0, b1);
                mma_tf32(acc[1][j][0], acc[1][j][1], acc[1][j][2], acc[1][j][3],
                         af[1][0], af[1][1], af[1][2], af[1][3], b0, b1);
            }
        }
        __syncthreads();
    }

    // ---- reduce norms: quad butterfly over lane%4 ----
#pragma unroll
    for (int i = 0; i < 2; i++)
#pragma unroll
        for (int h = 0; h < 2; h++) {
            pa2[i][h] += __shfl_xor_sync(0xffffffffu, pa2[i][h], 1);
            pa2[i][h] += __shfl_xor_sync(0xffffffffu, pa2[i][h], 2);
        }
    float x2v[7][2];
#pragma unroll
    for (int j = 0; j < 7; j++) {
        xb2[j] += __shfl_xor_sync(0xffffffffu, xb2[j], 1);
        xb2[j] += __shfl_xor_sync(0xffffffffu, xb2[j], 2);
        // transpose within warp: x2 for column (qc*2+q) lives in lane (qc*2+q)*4
        x2v[j][0] = __shfl_sync(0xffffffffu, xb2[j], (qc * 2    ) << 2);
        x2v[j][1] = __shfl_sync(0xffffffffu, xb2[j], (qc * 2 + 1) << 2);
    }

    // ---- epilogue: act = log((dist+1)/(dist+EPS)) -> smem transpose ----
    float* Es = smf;   // reuse: 128 x 113 floats = 14464 <= 16896
#pragma unroll
    for (int i = 0; i < 2; i++)
#pragma unroll
        for (int j = 0; j < 7; j++)
#pragma unroll
            for (int r = 0; r < 4; r++) {
                int rl = mw + 16*i + qr + (r >> 1) * 8;
                int cl = nw + 8*j + qc * 2 + (r & 1);
                float dist = fmaxf(x2v[j][r & 1] - 2.f * acc[i][j][r] + pa2[i][r >> 1], 0.f);
                Es[rl * EPITCH + cl] = logf((dist + 1.0f) / (dist + EPS));
            }
    __syncthreads();

    // ---- coalesced store ----
    if (tid < 224) {
        const int col  = tid % NT;
        const int row0 = tid / NT;
        const int n    = nb + col;
        if (n < HW_SZ) {
#pragma unroll 4
            for (int row = row0; row < MT; row += 2) {
                int m = mb + row;
                if (m < P_SZ)
                    out[((size_t)b * P_SZ + m) * HW_SZ + n] = Es[row * EPITCH + col];
            }
        }
    }
}

extern "C" void kernel_launch(void* const* d_in, const int* in_sizes, int n_in,
                              void* d_out, int out_size) {
    const float* x = (const float*)d_in[0];   // (64, 512, 14, 14)
    const float* p = (const float*)d_in[1];   // (2000, 512, 1, 1)
    float* out = (float*)d_out;               // (64, 2000, 14, 14)

    cudaFuncSetAttribute(proto_mma, cudaFuncAttributeMaxDynamicSharedMemorySize, SMEM_BYTES);
    dim3 grid(2, 16, B_SZ);
    proto_mma<<<grid, 256, SMEM_BYTES>>>(x, p, out);
}

// round 5
// speedup vs baseline: 3.3220x; 1.0320x over previous
#include <cuda_runtime.h>
#include <cstdint>
#include <math.h>

#define EPS 1e-4f
#define B_SZ   64
#define C_SZ   512
#define HW_SZ  196
#define P_SZ   2000
#define MT     128
#define NT     112
#define KC     32
#define NSTAGE 16
#define APITCH 36
#define BPITCH 120
#define EPITCH 113

#define A_STG (MT*APITCH)              // 4608 floats
#define B_STG (KC*BPITCH)              // 3840 floats
#define SM_A0 0
#define SM_A1 A_STG
#define SM_B0 (2*A_STG)
#define SM_B1 (2*A_STG + B_STG)
#define SMEM_FLOATS (2*A_STG + 2*B_STG)   // 16896 floats
#define SMEM_BYTES  (SMEM_FLOATS*4)       // 67584 B

// global scratch for norms (no cudaMalloc allowed)
__device__ float g_x2p[8][B_SZ*HW_SZ];
__device__ float g_x2[B_SZ*HW_SZ];
__device__ float g_p2[2048];

static __device__ __forceinline__ uint32_t s2u(const void* p) {
    uint32_t a;
    asm("{ .reg .u64 t; cvta.to.shared.u64 t, %1; cvt.u32.u64 %0, t; }"
        : "=r"(a) : "l"(p));
    return a;
}

static __device__ __forceinline__ void cpa16(uint32_t dst, const void* src, int sz) {
    asm volatile("cp.async.cg.shared.global [%0], [%1], 16, %2;"
                 :: "r"(dst), "l"(src), "r"(sz));
}

static __device__ __forceinline__ void ldsm4(uint32_t& r0, uint32_t& r1,
                                             uint32_t& r2, uint32_t& r3, uint32_t a) {
    asm volatile("ldmatrix.sync.aligned.m8n8.x4.shared.b16 {%0,%1,%2,%3}, [%4];"
                 : "=r"(r0), "=r"(r1), "=r"(r2), "=r"(r3) : "r"(a));
}

static __device__ __forceinline__ void mma_tf32(
    float& c0, float& c1, float& c2, float& c3,
    uint32_t a0, uint32_t a1, uint32_t a2, uint32_t a3, float b0, float b1)
{
    asm volatile(
        "mma.sync.aligned.m16n8k8.row.col.f32.tf32.tf32.f32 "
        "{%0,%1,%2,%3}, {%4,%5,%6,%7}, {%8,%9}, {%0,%1,%2,%3};"
        : "+f"(c0), "+f"(c1), "+f"(c2), "+f"(c3)
        : "r"(a0), "r"(a1), "r"(a2), "r"(a3),
          "r"(__float_as_uint(b0)), "r"(__float_as_uint(b1)));
}

// ---- norm precompute (deterministic two-pass, no atomics) ----
__global__ void x2_part(const float* __restrict__ x) {
    int i = blockIdx.x * 256 + threadIdx.x;
    if (i >= B_SZ * HW_SZ) return;
    int b = i / HW_SZ, hw = i - b * HW_SZ;
    int z = blockIdx.y;
    const float* px = x + (size_t)b * C_SZ * HW_SZ + (size_t)z * 64 * HW_SZ + hw;
    float s = 0.f;
#pragma unroll 16
    for (int c = 0; c < 64; c++) {
        float v = px[(size_t)c * HW_SZ];
        s = fmaf(v, v, s);
    }
    g_x2p[z][i] = s;
}

__global__ void x2_reduce() {
    int i = blockIdx.x * 256 + threadIdx.x;
    if (i >= B_SZ * HW_SZ) return;
    float s = 0.f;
#pragma unroll
    for (int z = 0; z < 8; z++) s += g_x2p[z][i];
    g_x2[i] = s;
}

__global__ void p2_k(const float* __restrict__ p) {
    int row  = blockIdx.x * 8 + (threadIdx.x >> 5);
    int lane = threadIdx.x & 31;
    float s = 0.f;
    if (row < P_SZ) {
        const float* pr = p + (size_t)row * C_SZ;
#pragma unroll
        for (int t = lane; t < C_SZ; t += 32) {
            float v = pr[t];
            s = fmaf(v, v, s);
        }
    }
#pragma unroll
    for (int o = 16; o > 0; o >>= 1)
        s += __shfl_down_sync(0xffffffffu, s, o);
    if (row < P_SZ && lane == 0) g_p2[row] = s;
}

// ---- main fused GEMM + epilogue ----
__global__ __launch_bounds__(256, 2) void proto_mma(
    const float* __restrict__ x,
    const float* __restrict__ p,
    float* __restrict__ out)
{
    extern __shared__ float smf[];
    const uint32_t sb = s2u(smf);
    const int tid  = threadIdx.x;
    const int wid  = tid >> 5;
    const int lane = tid & 31;
    const int qr   = lane >> 2;
    const int qc   = lane & 3;
    const int nb   = blockIdx.x * NT;
    const int mb   = blockIdx.y * MT;
    const int b    = blockIdx.z;
    const int mw   = (wid >> 1) * 32;
    const int nw   = (wid & 1) * 56;
    const float* xb = x + (size_t)b * C_SZ * HW_SZ;

    // ldmatrix per-lane source row/col within A tile
    const int lrow = mw + (lane & 7) + 8 * ((lane >> 3) & 1);
    const int lcol = 4 * (lane >> 4);

    float acc[2][7][4];
#pragma unroll
    for (int i = 0; i < 2; i++)
#pragma unroll
        for (int j = 0; j < 7; j++)
#pragma unroll
            for (int r = 0; r < 4; r++) acc[i][j][r] = 0.f;

    auto load_stage = [&](int s) {
        const int buf = s & 1;
        const int kt  = s * KC;
        const uint32_t sA = sb + (buf ? SM_A1 : SM_A0) * 4;
        const uint32_t sB = sb + (buf ? SM_B1 : SM_B0) * 4;
#pragma unroll
        for (int l = 0; l < 4; l++) {
            int idx = tid + l * 256;
            int row = idx >> 3, j = idx & 7;
            int sz  = (mb + row < P_SZ) ? 16 : 0;
            cpa16(sA + (row * APITCH + j * 4) * 4,
                  p + (size_t)(mb + row) * C_SZ + kt + j * 4, sz);
        }
#pragma unroll
        for (int l = 0; l < 4; l++) {
            int idx = tid + l * 256;
            if (idx < 896) {
                int k = idx / 28, q = idx - k * 28;
                int n0 = nb + q * 4;
                int sz = (n0 <= HW_SZ - 4) ? 16 : 0;
                cpa16(sB + (k * BPITCH + q * 4) * 4,
                      xb + (size_t)(kt + k) * HW_SZ + n0, sz);
            }
        }
        asm volatile("cp.async.commit_group;" ::: "memory");
    };

    load_stage(0);

    for (int s = 0; s < NSTAGE; s++) {
        if (s + 1 < NSTAGE) load_stage(s + 1);
        else asm volatile("cp.async.commit_group;" ::: "memory");
        asm volatile("cp.async.wait_group 1;" ::: "memory");
        __syncthreads();

        const int buf = s & 1;
        const uint32_t sA = sb + (buf ? SM_A1 : SM_A0) * 4;
        const float* Bb = smf + (buf ? SM_B1 : SM_B0);
        const uint32_t aAddr = sA + (lrow * APITCH + lcol) * 4;
        const float* bp = Bb + qc * BPITCH + nw + qr;

#pragma unroll
        for (int ks = 0; ks < 4; ks++) {
            const int k8 = ks * 8;
            uint32_t af[2][4];
            ldsm4(af[0][0], af[0][1], af[0][2], af[0][3], aAddr + k8 * 4);
            ldsm4(af[1][0], af[1][1], af[1][2], af[1][3],
                  aAddr + (16 * APITCH + k8) * 4);
#pragma unroll
            for (int j = 0; j < 7; j++) {
                float b0 = bp[ k8      * BPITCH + 8*j];
                float b1 = bp[(k8 + 4) * BPITCH + 8*j];
                mma_tf32(acc[0][j][0], acc[0][j][1], acc[0][j][2], acc[0][j][3],
                         af[0][0], af[0][1], af[0][2], af[0][3], b0, b1);
                mma_tf32(acc[1][j][0], acc[1][j][1], acc[1][j][2], acc[1][j][3],
                         af[1][0], af[1][1], af[1][2], af[1][3], b0, b1);
            }
        }
        __syncthreads();
    }

    // ---- fetch precomputed norms ----
    float pa2v[2][2];
#pragma unroll
    for (int i = 0; i < 2; i++)
#pragma unroll
        for (int h = 0; h < 2; h++) {
            int row = mb + mw + 16*i + 8*h + qr;
            pa2v[i][h] = (row < P_SZ) ? g_p2[row] : 0.f;
        }
    float x2v[7][2];
#pragma unroll
    for (int j = 0; j < 7; j++)
#pragma unroll
        for (int h = 0; h < 2; h++) {
            int n = nb + nw + 8*j + qc*2 + h;
            x2v[j][h] = (n < HW_SZ) ? g_x2[b * HW_SZ + n] : 0.f;
        }

    // ---- epilogue: act = log((dist+1)/(dist+EPS)) -> smem transpose ----
    float* Es = smf;   // 128 x 113 floats = 14464 <= 16896
#pragma unroll
    for (int i = 0; i < 2; i++)
#pragma unroll
        for (int j = 0; j < 7; j++)
#pragma unroll
            for (int r = 0; r < 4; r++) {
                int rl = mw + 16*i + qr + (r >> 1) * 8;
                int cl = nw + 8*j + qc * 2 + (r & 1);
                float dist = fmaxf(x2v[j][r & 1] - 2.f * acc[i][j][r] + pa2v[i][r >> 1], 0.f);
                Es[rl * EPITCH + cl] = logf((dist + 1.0f) / (dist + EPS));
            }
    __syncthreads();

    // ---- coalesced store ----
    if (tid < 224) {
        const int col  = tid % NT;
        const int row0 = tid / NT;
        const int n    = nb + col;
        if (n < HW_SZ) {
#pragma unroll 4
            for (int row = row0; row < MT; row += 2) {
                int m = mb + row;
                if (m < P_SZ)
                    out[((size_t)b * P_SZ + m) * HW_SZ + n] = Es[row * EPITCH + col];
            }
        }
    }
}

extern "C" void kernel_launch(void* const* d_in, const int* in_sizes, int n_in,
                              void* d_out, int out_size) {
    const float* x = (const float*)d_in[0];   // (64, 512, 14, 14)
    const float* p = (const float*)d_in[1];   // (2000, 512, 1, 1)
    float* out = (float*)d_out;               // (64, 2000, 14, 14)

    x2_part<<<dim3(49, 8), 256>>>(x);
    x2_reduce<<<49, 256>>>();
    p2_k<<<250, 256>>>(p);

    cudaFuncSetAttribute(proto_mma, cudaFuncAttributeMaxDynamicSharedMemorySize, SMEM_BYTES);
    dim3 grid(2, 16, B_SZ);
    proto_mma<<<grid, 256, SMEM_BYTES>>>(x, p, out);
}